// round 11
// baseline (speedup 1.0000x reference)
#include <cuda_runtime.h>
#include <cuda_fp16.h>
#include <cstdint>

#define BDIM 32
#define PDIM 1024
#define VDIM 100
#define EDIM 512
#define HDIM 512
#define EPSV 1e-5f
#define PPAD (PDIM + 2)

// GEMM tiling: CTA 64x256, fp16 mma.sync, shared-B across taps, 2-stage, 2 CTA/SM
#define TM 64
#define TN 256
#define TKH 64                             // K elems (fp16) per chunk = 128B rows
#define NCHUNK (HDIM / TKH)                // 8
#define A_TAP_BYTES (TM * 128)             // 8192 per tap
#define A_BYTES (3 * A_TAP_BYTES)          // 24576
#define B_ROWS_PAD 260                     // 256 + 2 halo, padded
#define B_BYTES (B_ROWS_PAD * 128)         // 33280
#define STAGE_BYTES (A_BYTES + B_BYTES)    // 57856
#define GEMM_SMEM (2 * STAGE_BYTES)        // 115712  (2 CTAs = 226 KB/SM)
#define STAGE_CHUNKS (STAGE_BYTES / 16)    // 3616
#define A_CHUNKS (A_BYTES / 16)            // 1536
// epilogue smem reuse: fp16 post-bias tile 64 x 264 halfs = 33792 B
#define TSH 264
#define NPB (PDIM / TN)                    // 4 p-blocks per batch
#define SPAN 2304                          // max frames per p-block (256 * 9)

// ---------------- scratch (static device globals) ----------------
__device__ float  g_W1t[3 * EDIM * HDIM];            // [k][e][h]
__device__ float  g_Atab[3 * VDIM * HDIM];           // [k][v][h]
__device__ float  g_c1[HDIM];
__device__ float  g_c2[HDIM];
__device__ __half g_W2k[3 * HDIM * HDIM];            // [tap][h][h'] fp16, K-major
__device__ __half g_y1t[(size_t)BDIM * PPAD * HDIM]; // [b][p+1][h'] fp16, halo rows zero
__device__ int2   g_sd[BDIM * PDIM];                 // per-phoneme (start, dur)
__device__ int    g_total[BDIM];                     // per-batch total frames
__device__ unsigned char g_fmap[BDIM * NPB * SPAN];  // frame -> tile-local phoneme idx

// ---------------- PTX helpers (base ISA only) ----------------
__device__ __forceinline__ uint32_t smem_u32(const void* p) {
    uint32_t a;
    asm("{ .reg .u64 t; cvta.to.shared.u64 t, %1; cvt.u32.u64 %0, t; }" : "=r"(a) : "l"(p));
    return a;
}
__device__ __forceinline__ void cp_async16(uint32_t s, const void* g) {
    asm volatile("cp.async.cg.shared.global [%0], [%1], 16;" :: "r"(s), "l"(g) : "memory");
}
#define CP_COMMIT() asm volatile("cp.async.commit_group;" ::: "memory")
#define CP_WAIT1()  asm volatile("cp.async.wait_group 1;" ::: "memory")

#define LDSM_X4(r0, r1, r2, r3, addr)                                        \
    asm volatile("ldmatrix.sync.aligned.m8n8.x4.shared.b16 {%0,%1,%2,%3}, [%4];" \
        : "=r"(r0), "=r"(r1), "=r"(r2), "=r"(r3) : "r"(addr))

__device__ __forceinline__ void mma16816(float* d, uint32_t a0, uint32_t a1,
                                         uint32_t a2, uint32_t a3,
                                         uint32_t b0, uint32_t b1) {
    asm volatile(
        "mma.sync.aligned.m16n8k16.row.col.f32.f16.f16.f32 "
        "{%0,%1,%2,%3}, {%4,%5,%6,%7}, {%8,%9}, {%0,%1,%2,%3};"
        : "+f"(d[0]), "+f"(d[1]), "+f"(d[2]), "+f"(d[3])
        : "r"(a0), "r"(a1), "r"(a2), "r"(a3), "r"(b0), "r"(b1));
}

__device__ __forceinline__ uint32_t sw128(uint32_t off) { return off ^ ((off >> 3) & 0x70); }

// ---------------- launch 0: fold-BN vectors + W1 transpose + y1t halo zero ----------------
__global__ void k_prep(const float* __restrict__ w1,
                       const float* b1, const float* g1, const float* be1,
                       const float* m1, const float* v1,
                       const float* b2, const float* g2, const float* be2,
                       const float* m2, const float* v2) {
    int bx = blockIdx.x, tid = threadIdx.x;
    if (bx < 3072) {
        // W1 transpose (H,E,3) -> [k][e][h]
        int idx = bx * 256 + tid;
        int h = idx / (EDIM * 3);
        int r = idx % (EDIM * 3);
        int e = r / 3;
        int k = r % 3;
        g_W1t[(k * EDIM + e) * HDIM + h] = w1[idx];
    } else {
        int zb = bx - 3072;                 // 0..63: zero halo rows of y1t (as uint32 words)
        int i = zb * 256 + tid;             // 16384 words = 32 b * 2 rows * 256 words
        int b = i / 512;
        int r = i % 512;
        int p = (r < 256) ? 0 : (PPAD - 1);
        int hw = r % 256;
        ((uint32_t*)g_y1t)[((size_t)b * PPAD + p) * (HDIM / 2) + hw] = 0u;
        if (zb == 0) {
#pragma unroll
            for (int q = 0; q < 2; ++q) {
                int hh = tid + q * 256;
                float s1 = g1[hh] * rsqrtf(v1[hh] + EPSV);
                g_c1[hh] = b1[hh] * s1 + be1[hh] - m1[hh] * s1;
                float s2 = g2[hh] * rsqrtf(v2[hh] + EPSV);
                g_c2[hh] = b2[hh] * s2 + be2[hh] - m2[hh] * s2;
            }
        }
    }
}

// ---------------- launch 1: Atab + W2k(fp16) + duration scan + fmap (fused) ----------------
__global__ void k_tab(const float* __restrict__ emb,
                      const float* __restrict__ g1, const float* __restrict__ v1,
                      const float* __restrict__ w2,
                      const float* __restrict__ g2, const float* __restrict__ v2,
                      const int* __restrict__ durs) {
    __shared__ float es[EDIM];
    __shared__ int bstart[NPB];
    int bx = blockIdx.x, tid = threadIdx.x;   // 512 threads
    if (bx < 300) {
        // Atab[k][v][h] = scale1[h]*(emb[v] . W1[h,:,k])
        int v = bx / 3, k = bx % 3, h = tid;
        es[h] = emb[v * EDIM + h];
        __syncthreads();
        const float* w = g_W1t + (size_t)k * EDIM * HDIM + h;
        float acc = 0.f;
#pragma unroll 8
        for (int e = 0; e < EDIM; ++e)
            acc += es[e] * w[(size_t)e * HDIM];
        float scale = g1[h] * rsqrtf(v1[h] + EPSV);
        g_Atab[((size_t)k * VDIM + v) * HDIM + h] = acc * scale;
    } else if (bx < 1068) {
        // W2k[tap][h][hp] = fp16(scale2[h]*W2[h,hp,tap]), packed pairs
        int pidx = (bx - 300) * 512 + tid;       // over 3*512*256 half2 pairs
        int tap = pidx / (HDIM * (HDIM / 2));
        int r = pidx % (HDIM * (HDIM / 2));
        int h = r / (HDIM / 2);
        int hp = (r % (HDIM / 2)) * 2;
        float s2 = g2[h] * rsqrtf(v2[h] + EPSV);
        float v0 = w2[h * HDIM * 3 + hp * 3 + tap] * s2;
        float v1f = w2[h * HDIM * 3 + (hp + 1) * 3 + tap] * s2;
        ((half2*)g_W2k)[pidx] = __floats2half2_rn(v0, v1f);
    } else {
        // duration scan for batch b: (start, dur) per phoneme + total + fmap bytes
        int b = bx - 1068;                       // 0..31
        int* ps = (int*)es;
        int d0 = durs[b * PDIM + 2 * tid];
        int d1 = durs[b * PDIM + 2 * tid + 1];
        ps[tid] = d0 + d1;
        __syncthreads();
        for (int off = 1; off < 512; off <<= 1) {
            int t = (tid >= off) ? ps[tid - off] : 0;
            __syncthreads();
            ps[tid] += t;
            __syncthreads();
        }
        int incl = ps[tid];
        int excl = incl - d0 - d1;
        g_sd[b * PDIM + 2 * tid]     = make_int2(excl, d0);
        g_sd[b * PDIM + 2 * tid + 1] = make_int2(excl + d0, d1);
        if (tid == 511) g_total[b] = incl;
        if (tid < NPB) bstart[tid] = (tid == 0) ? 0 : ps[tid * (TN / 2) - 1];
        __syncthreads();
        // fmap: tile-local phoneme index per frame (both phonemes in same p-block)
        int p_ = 2 * tid;
        int pb = p_ >> 8;
        unsigned char* fm = g_fmap + (b * NPB + pb) * SPAN;
        int rel = excl - bstart[pb];
        for (int i = 0; i < d0; ++i) fm[rel + i] = (unsigned char)(p_ & 255);
        rel += d0;
        for (int i = 0; i < d1; ++i) fm[rel + i] = (unsigned char)((p_ + 1) & 255);
    }
}

// ---------------- launch 2: y1 table lookups -> transposed, padded, fp16 ----------------
__global__ void k_y1(const int* __restrict__ ids) {
    __shared__ int sid[18];
    int b = blockIdx.x;
    int p0 = blockIdx.y * 16;
    int tid = threadIdx.x;   // 256
    if (tid < 18) {
        int q = p0 - 1 + tid;
        sid[tid] = (q >= 0 && q < PDIM) ? ids[b * PDIM + q] : -1;
    }
    __syncthreads();
    int h = tid * 2;                       // each thread: one half2 pair
    float c0 = g_c1[h], c1 = g_c1[h + 1];
    half2* out = (half2*)g_y1t;
#pragma unroll
    for (int pl = 0; pl < 16; ++pl) {
        int i0 = sid[pl], i1 = sid[pl + 1], i2 = sid[pl + 2];
        float v0 = c0, v1 = c1;
        if (i0 >= 0) {
            const float* a = g_Atab + (0 * VDIM + i0) * HDIM + h;
            v0 += a[0]; v1 += a[1];
        }
        if (i1 >= 0) {
            const float* a = g_Atab + (1 * VDIM + i1) * HDIM + h;
            v0 += a[0]; v1 += a[1];
        }
        if (i2 >= 0) {
            const float* a = g_Atab + (2 * VDIM + i2) * HDIM + h;
            v0 += a[0]; v1 += a[1];
        }
        v0 = fmaxf(v0, 0.f);
        v1 = fmaxf(v1, 0.f);
        out[((size_t)b * PPAD + p0 + pl + 1) * (HDIM / 2) + tid] = __floats2half2_rn(v0, v1);
    }
}

// ---------------- launch 3: conv2 GEMM + fp16-staged coalesced upsample epilogue ----------------
__global__ __launch_bounds__(256, 2) void k_gemm(float* __restrict__ out, int F) {
    extern __shared__ __align__(1024) char smem[];
    uint32_t sb = smem_u32(smem);
    int tid = threadIdx.x;
    int lane = tid & 31, wid = tid >> 5;   // 8 warps
    int wm = wid & 1;          // 2 m-tiles of 32
    int wn = wid >> 1;         // 4 n-tiles of 64
    int p0 = blockIdx.x * TN;
    int h0 = blockIdx.y * TM;
    int b = blockIdx.z;

    // ---- per-lane ldmatrix address components (128B K-major rows, SW128) ----
    uint32_t aBase[2], aXor[2];
#pragma unroll
    for (int fi = 0; fi < 2; ++fi) {
        int row = wm * 32 + fi * 16 + (lane & 15);
        aBase[fi] = row * 128;
        aXor[fi] = (row & 7) * 16;
    }
    uint32_t aK0 = (lane >> 4) * 16;

    int nb = (lane & 7) | ((lane & 16) >> 1);
    uint32_t bK0 = ((lane >> 3) & 1) * 16;
    int bRow[4];
#pragma unroll
    for (int half = 0; half < 4; ++half)
        bRow[half] = wn * 64 + half * 16 + nb;

    // ---- stage loader: 3 A tap tiles (64 rows each) + shared B halo tile ----
    auto load_stage = [&](int c, int s) {
        int kk = c * TKH;
        uint32_t st = sb + s * STAGE_BYTES;
#pragma unroll
        for (int j = 0; j < 15; ++j) {
            int i = tid + j * 256;
            if (i >= STAGE_CHUNKS) break;
            if (i < A_CHUNKS) {                // A: 3 tap tiles, 64 rows x 128B
                int tap = i >> 9;
                int r = i & 511;
                int row = r >> 3, seg = r & 7;
                const __half* g = g_W2k + ((size_t)tap * HDIM + h0 + row) * HDIM + kk + seg * 8;
                cp_async16(st + tap * A_TAP_BYTES + sw128((uint32_t)(row * 128 + seg * 16)), g);
            } else {                           // B: halo rows p0-1 .. p0+256 (+pad clamp)
                int ii = i - A_CHUNKS;
                int row = ii >> 3, seg = ii & 7;
                int rowc = row < 258 ? row : 257;
                const __half* g = g_y1t + ((size_t)b * PPAD + p0 + rowc) * HDIM + kk + seg * 8;
                cp_async16(st + A_BYTES + sw128((uint32_t)(row * 128 + seg * 16)), g);
            }
        }
    };

    float acc[2][8][4];
#pragma unroll
    for (int fi = 0; fi < 2; ++fi)
#pragma unroll
        for (int ni = 0; ni < 8; ++ni)
#pragma unroll
            for (int q = 0; q < 4; ++q) acc[fi][ni][q] = 0.f;

    load_stage(0, 0); CP_COMMIT();
    load_stage(1, 1); CP_COMMIT();

    for (int c = 0; c < NCHUNK; ++c) {
        CP_WAIT1();
        __syncthreads();
        uint32_t st = sb + (c & 1) * STAGE_BYTES;
        uint32_t stB = st + A_BYTES;
#pragma unroll
        for (int tap = 0; tap < 3; ++tap) {
            uint32_t stA = st + tap * A_TAP_BYTES;
#pragma unroll
            for (int j = 0; j < 4; ++j) {      // 4 k16 steps per 128B row
                uint32_t a[2][4], bf[4][4];
#pragma unroll
                for (int fi = 0; fi < 2; ++fi) {
                    uint32_t addr = stA + aBase[fi] + ((aK0 + j * 32) ^ aXor[fi]);
                    LDSM_X4(a[fi][0], a[fi][1], a[fi][2], a[fi][3], addr);
                }
#pragma unroll
                for (int half = 0; half < 4; ++half) {
                    int row = bRow[half] + tap;
                    uint32_t addr = stB + row * 128 + ((bK0 + j * 32) ^ ((row & 7) * 16));
                    LDSM_X4(bf[half][0], bf[half][1], bf[half][2], bf[half][3], addr);
                }
#pragma unroll
                for (int fi = 0; fi < 2; ++fi)
#pragma unroll
                    for (int ni = 0; ni < 8; ++ni)
                        mma16816(acc[fi][ni], a[fi][0], a[fi][1], a[fi][2], a[fi][3],
                                 bf[ni >> 1][(ni & 1) * 2], bf[ni >> 1][(ni & 1) * 2 + 1]);
            }
        }
        __syncthreads();
        if (c + 2 < NCHUNK) load_stage(c + 2, c & 1);
        CP_COMMIT();
    }

    // ---- epilogue: bias+relu -> fp16 smem tile, then coalesced upsample copy ----
    __syncthreads();                           // all compute done; safe to reuse stage smem
    __half* stile = (__half*)smem;             // [64][TSH]

    {
        int hl = wm * 32 + (lane >> 2);
        int pl = wn * 64 + (lane & 3) * 2;
#pragma unroll
        for (int fi = 0; fi < 2; ++fi)
#pragma unroll
            for (int rr = 0; rr < 2; ++rr) {
                int hh = hl + fi * 16 + rr * 8;
                float cc = g_c2[h0 + hh];
                half2* dst = (half2*)(stile + hh * TSH + pl);
#pragma unroll
                for (int ni = 0; ni < 8; ++ni) {
                    float v0 = fmaxf(acc[fi][ni][rr * 2 + 0] + cc, 0.f);
                    float v1 = fmaxf(acc[fi][ni][rr * 2 + 1] + cc, 0.f);
                    dst[ni * 4] = __floats2half2_rn(v0, v1);
                }
            }
    }

    bool lastblk = (p0 + TN >= PDIM);
    int fs = g_sd[b * PDIM + p0].x;
    int fe = lastblk ? g_total[b] : g_sd[b * PDIM + p0 + TN].x;
    int L = fe - fs;
    int Lw = lastblk ? (F - fs) : L;           // last block also zeroes the masked tail
    __syncthreads();

    const unsigned char* fmap = g_fmap + ((size_t)b * NPB + (p0 >> 8)) * SPAN;
    for (int h = wid; h < TM; h += 8) {
        float* orow = out + ((size_t)b * HDIM + h0 + h) * F + fs;
        const __half* srow = stile + h * TSH;
        for (int f = lane; f < Lw; f += 32)
            orow[f] = (f < L) ? __half2float(srow[fmap[f]]) : 0.f;
    }
}

// ---------------- launch ----------------
extern "C" void kernel_launch(void* const* d_in, const int* in_sizes, int n_in,
                              void* d_out, int out_size) {
    const int* ids   = (const int*)d_in[0];
    const int* durs  = (const int*)d_in[1];
    const float* emb = (const float*)d_in[2];
    const float* w1  = (const float*)d_in[3];
    const float* b1  = (const float*)d_in[4];
    const float* g1  = (const float*)d_in[5];
    const float* be1 = (const float*)d_in[6];
    const float* m1  = (const float*)d_in[7];
    const float* v1  = (const float*)d_in[8];
    const float* w2  = (const float*)d_in[9];
    const float* b2  = (const float*)d_in[10];
    const float* g2  = (const float*)d_in[11];
    const float* be2 = (const float*)d_in[12];
    const float* m2  = (const float*)d_in[13];
    const float* v2  = (const float*)d_in[14];
    float* out = (float*)d_out;
    int F = out_size / (BDIM * HDIM);

    cudaFuncSetAttribute(k_gemm, cudaFuncAttributeMaxDynamicSharedMemorySize, GEMM_SMEM);

    k_prep<<<3072 + 64, 256>>>(w1, b1, g1, be1, m1, v1, b2, g2, be2, m2, v2);   // launch 0
    k_tab<<<300 + 768 + 32, 512>>>(emb, g1, v1, w2, g2, v2, durs);              // launch 1
    k_y1<<<dim3(BDIM, PDIM / 16), 256>>>(ids);                                  // launch 2
    k_gemm<<<dim3(PDIM / TN, HDIM / TM, BDIM), 256, GEMM_SMEM>>>(out, F);       // launch 3 (profiled)
}

// round 12
// speedup vs baseline: 1.7454x; 1.7454x over previous
#include <cuda_runtime.h>
#include <cuda_fp16.h>
#include <cstdint>

#define BDIM 32
#define PDIM 1024
#define VDIM 100
#define EDIM 512
#define HDIM 512
#define EPSV 1e-5f
#define PPAD (PDIM + 2)

// GEMM tiling: CTA 64x256, fp16 mma.sync, shared-B across taps, 2-stage, 2 CTA/SM
#define TM 64
#define TN 256
#define TKH 64                             // K elems (fp16) per chunk = 128B rows
#define NCHUNK (HDIM / TKH)                // 8
#define A_TAP_BYTES (TM * 128)             // 8192 per tap
#define A_BYTES (3 * A_TAP_BYTES)          // 24576
#define B_ROWS_PAD 260                     // 256 + 2 halo, padded
#define B_BYTES (B_ROWS_PAD * 128)         // 33280
#define STAGE_BYTES (A_BYTES + B_BYTES)    // 57856
#define GEMM_SMEM (2 * STAGE_BYTES)        // 115712  (2 CTAs = 226 KB/SM)
#define STAGE_CHUNKS (STAGE_BYTES / 16)    // 3616
#define A_CHUNKS (A_BYTES / 16)            // 1536
// epilogue smem reuse: fp32 post-bias tile 64 x 258 floats + fmap bytes
#define TS 258
#define TILE_BYTES (TM * TS * 4)           // 66048
#define NPB (PDIM / TN)                    // 4 p-blocks per batch
#define SPAN 2304                          // max frames per p-block (256 * 9)

// ---------------- scratch (static device globals) ----------------
__device__ float  g_W1t[3 * EDIM * HDIM];            // [k][e][h]
__device__ float  g_Atab[3 * VDIM * HDIM];           // [k][v][h]
__device__ float  g_c1[HDIM];
__device__ float  g_c2[HDIM];
__device__ __half g_W2k[3 * HDIM * HDIM];            // [tap][h][h'] fp16, K-major
__device__ __half g_y1t[(size_t)BDIM * PPAD * HDIM]; // [b][p+1][h'] fp16, halo rows zero
__device__ int2   g_sd[BDIM * PDIM];                 // per-phoneme (start, dur)
__device__ int    g_total[BDIM];                     // per-batch total frames
__device__ unsigned char g_fmap[BDIM * NPB * SPAN];  // frame -> tile-local phoneme idx

// ---------------- PTX helpers (base ISA only) ----------------
__device__ __forceinline__ uint32_t smem_u32(const void* p) {
    uint32_t a;
    asm("{ .reg .u64 t; cvta.to.shared.u64 t, %1; cvt.u32.u64 %0, t; }" : "=r"(a) : "l"(p));
    return a;
}
__device__ __forceinline__ void cp_async16(uint32_t s, const void* g) {
    asm volatile("cp.async.cg.shared.global [%0], [%1], 16;" :: "r"(s), "l"(g) : "memory");
}
#define CP_COMMIT() asm volatile("cp.async.commit_group;" ::: "memory")
#define CP_WAIT1()  asm volatile("cp.async.wait_group 1;" ::: "memory")
#define CP_WAIT0()  asm volatile("cp.async.wait_group 0;" ::: "memory")

#define LDSM_X4(r0, r1, r2, r3, addr)                                        \
    asm volatile("ldmatrix.sync.aligned.m8n8.x4.shared.b16 {%0,%1,%2,%3}, [%4];" \
        : "=r"(r0), "=r"(r1), "=r"(r2), "=r"(r3) : "r"(addr))

__device__ __forceinline__ void mma16816(float* d, uint32_t a0, uint32_t a1,
                                         uint32_t a2, uint32_t a3,
                                         uint32_t b0, uint32_t b1) {
    asm volatile(
        "mma.sync.aligned.m16n8k16.row.col.f32.f16.f16.f32 "
        "{%0,%1,%2,%3}, {%4,%5,%6,%7}, {%8,%9}, {%0,%1,%2,%3};"
        : "+f"(d[0]), "+f"(d[1]), "+f"(d[2]), "+f"(d[3])
        : "r"(a0), "r"(a1), "r"(a2), "r"(a3), "r"(b0), "r"(b1));
}

__device__ __forceinline__ uint32_t sw128(uint32_t off) { return off ^ ((off >> 3) & 0x70); }

// ---------------- launch 0: fold-BN vectors + W1 transpose + y1t halo zero ----------------
__global__ void k_prep(const float* __restrict__ w1,
                       const float* b1, const float* g1, const float* be1,
                       const float* m1, const float* v1,
                       const float* b2, const float* g2, const float* be2,
                       const float* m2, const float* v2) {
    int bx = blockIdx.x, tid = threadIdx.x;
    if (bx < 3072) {
        // W1 transpose (H,E,3) -> [k][e][h]
        int idx = bx * 256 + tid;
        int h = idx / (EDIM * 3);
        int r = idx % (EDIM * 3);
        int e = r / 3;
        int k = r % 3;
        g_W1t[(k * EDIM + e) * HDIM + h] = w1[idx];
    } else {
        int zb = bx - 3072;                 // 0..63: zero halo rows of y1t (as uint32 words)
        int i = zb * 256 + tid;             // 16384 words = 32 b * 2 rows * 256 words
        int b = i / 512;
        int r = i % 512;
        int p = (r < 256) ? 0 : (PPAD - 1);
        int hw = r % 256;
        ((uint32_t*)g_y1t)[((size_t)b * PPAD + p) * (HDIM / 2) + hw] = 0u;
        if (zb == 0) {
#pragma unroll
            for (int q = 0; q < 2; ++q) {
                int hh = tid + q * 256;
                float s1 = g1[hh] * rsqrtf(v1[hh] + EPSV);
                g_c1[hh] = b1[hh] * s1 + be1[hh] - m1[hh] * s1;
                float s2 = g2[hh] * rsqrtf(v2[hh] + EPSV);
                g_c2[hh] = b2[hh] * s2 + be2[hh] - m2[hh] * s2;
            }
        }
    }
}

// ---------------- launch 1: Atab + W2k(fp16) + duration scan + fmap (fused) ----------------
__global__ void k_tab(const float* __restrict__ emb,
                      const float* __restrict__ g1, const float* __restrict__ v1,
                      const float* __restrict__ w2,
                      const float* __restrict__ g2, const float* __restrict__ v2,
                      const int* __restrict__ durs) {
    __shared__ float es[EDIM];
    __shared__ int bstart[NPB];
    int bx = blockIdx.x, tid = threadIdx.x;   // 512 threads
    if (bx < 300) {
        // Atab[k][v][h] = scale1[h]*(emb[v] . W1[h,:,k])
        int v = bx / 3, k = bx % 3, h = tid;
        es[h] = emb[v * EDIM + h];
        __syncthreads();
        const float* w = g_W1t + (size_t)k * EDIM * HDIM + h;
        float acc = 0.f;
#pragma unroll 8
        for (int e = 0; e < EDIM; ++e)
            acc += es[e] * w[(size_t)e * HDIM];
        float scale = g1[h] * rsqrtf(v1[h] + EPSV);
        g_Atab[((size_t)k * VDIM + v) * HDIM + h] = acc * scale;
    } else if (bx < 1068) {
        // W2k[tap][h][hp] = fp16(scale2[h]*W2[h,hp,tap]), packed pairs
        int pidx = (bx - 300) * 512 + tid;       // over 3*512*256 half2 pairs
        int tap = pidx / (HDIM * (HDIM / 2));
        int r = pidx % (HDIM * (HDIM / 2));
        int h = r / (HDIM / 2);
        int hp = (r % (HDIM / 2)) * 2;
        float s2 = g2[h] * rsqrtf(v2[h] + EPSV);
        float v0 = w2[h * HDIM * 3 + hp * 3 + tap] * s2;
        float v1f = w2[h * HDIM * 3 + (hp + 1) * 3 + tap] * s2;
        ((half2*)g_W2k)[pidx] = __floats2half2_rn(v0, v1f);
    } else {
        // duration scan for batch b: (start, dur) per phoneme + total + fmap bytes
        int b = bx - 1068;                       // 0..31
        int* ps = (int*)es;
        int d0 = durs[b * PDIM + 2 * tid];
        int d1 = durs[b * PDIM + 2 * tid + 1];
        ps[tid] = d0 + d1;
        __syncthreads();
        for (int off = 1; off < 512; off <<= 1) {
            int t = (tid >= off) ? ps[tid - off] : 0;
            __syncthreads();
            ps[tid] += t;
            __syncthreads();
        }
        int incl = ps[tid];
        int excl = incl - d0 - d1;
        g_sd[b * PDIM + 2 * tid]     = make_int2(excl, d0);
        g_sd[b * PDIM + 2 * tid + 1] = make_int2(excl + d0, d1);
        if (tid == 511) g_total[b] = incl;
        if (tid < NPB) bstart[tid] = (tid == 0) ? 0 : ps[tid * (TN / 2) - 1];
        __syncthreads();
        // fmap: tile-local phoneme index per frame (both phonemes in same p-block)
        int p_ = 2 * tid;
        int pb = p_ >> 8;
        unsigned char* fm = g_fmap + (b * NPB + pb) * SPAN;
        int rel = excl - bstart[pb];
        for (int i = 0; i < d0; ++i) fm[rel + i] = (unsigned char)(p_ & 255);
        rel += d0;
        for (int i = 0; i < d1; ++i) fm[rel + i] = (unsigned char)((p_ + 1) & 255);
    }
}

// ---------------- launch 2: y1 table lookups -> transposed, padded, fp16 ----------------
__global__ void k_y1(const int* __restrict__ ids) {
    __shared__ int sid[18];
    int b = blockIdx.x;
    int p0 = blockIdx.y * 16;
    int tid = threadIdx.x;   // 256
    if (tid < 18) {
        int q = p0 - 1 + tid;
        sid[tid] = (q >= 0 && q < PDIM) ? ids[b * PDIM + q] : -1;
    }
    __syncthreads();
    int h = tid * 2;                       // each thread: one half2 pair
    float c0 = g_c1[h], c1 = g_c1[h + 1];
    half2* out = (half2*)g_y1t;
#pragma unroll
    for (int pl = 0; pl < 16; ++pl) {
        int i0 = sid[pl], i1 = sid[pl + 1], i2 = sid[pl + 2];
        float v0 = c0, v1 = c1;
        if (i0 >= 0) {
            const float* a = g_Atab + (0 * VDIM + i0) * HDIM + h;
            v0 += a[0]; v1 += a[1];
        }
        if (i1 >= 0) {
            const float* a = g_Atab + (1 * VDIM + i1) * HDIM + h;
            v0 += a[0]; v1 += a[1];
        }
        if (i2 >= 0) {
            const float* a = g_Atab + (2 * VDIM + i2) * HDIM + h;
            v0 += a[0]; v1 += a[1];
        }
        v0 = fmaxf(v0, 0.f);
        v1 = fmaxf(v1, 0.f);
        out[((size_t)b * PPAD + p0 + pl + 1) * (HDIM / 2) + tid] = __floats2half2_rn(v0, v1);
    }
}

// ---------------- launch 3: conv2 GEMM + fp32-staged coalesced upsample epilogue ----------------
__global__ __launch_bounds__(256, 2) void k_gemm(float* __restrict__ out, int F) {
    extern __shared__ __align__(1024) char smem[];
    uint32_t sb = smem_u32(smem);
    int tid = threadIdx.x;
    int lane = tid & 31, wid = tid >> 5;   // 8 warps
    int wm = wid & 1;          // 2 m-tiles of 32
    int wn = wid >> 1;         // 4 n-tiles of 64
    int p0 = blockIdx.x * TN;
    int h0 = blockIdx.y * TM;
    int b = blockIdx.z;

    // ---- per-lane ldmatrix address components (128B K-major rows, SW128) ----
    uint32_t aBase[2], aXor[2];
#pragma unroll
    for (int fi = 0; fi < 2; ++fi) {
        int row = wm * 32 + fi * 16 + (lane & 15);
        aBase[fi] = row * 128;
        aXor[fi] = (row & 7) * 16;
    }
    uint32_t aK0 = (lane >> 4) * 16;

    int nb = (lane & 7) | ((lane & 16) >> 1);
    uint32_t bK0 = ((lane >> 3) & 1) * 16;
    int bRow[4];
#pragma unroll
    for (int half = 0; half < 4; ++half)
        bRow[half] = wn * 64 + half * 16 + nb;

    // ---- stage loader: 3 A tap tiles (64 rows each) + shared B halo tile ----
    auto load_stage = [&](int c, int s) {
        int kk = c * TKH;
        uint32_t st = sb + s * STAGE_BYTES;
#pragma unroll
        for (int j = 0; j < 15; ++j) {
            int i = tid + j * 256;
            if (i >= STAGE_CHUNKS) break;
            if (i < A_CHUNKS) {                // A: 3 tap tiles, 64 rows x 128B
                int tap = i >> 9;
                int r = i & 511;
                int row = r >> 3, seg = r & 7;
                const __half* g = g_W2k + ((size_t)tap * HDIM + h0 + row) * HDIM + kk + seg * 8;
                cp_async16(st + tap * A_TAP_BYTES + sw128((uint32_t)(row * 128 + seg * 16)), g);
            } else {                           // B: halo rows p0-1 .. p0+256 (+pad clamp)
                int ii = i - A_CHUNKS;
                int row = ii >> 3, seg = ii & 7;
                int rowc = row < 258 ? row : 257;
                const __half* g = g_y1t + ((size_t)b * PPAD + p0 + rowc) * HDIM + kk + seg * 8;
                cp_async16(st + A_BYTES + sw128((uint32_t)(row * 128 + seg * 16)), g);
            }
        }
    };

    float acc[2][8][4];
#pragma unroll
    for (int fi = 0; fi < 2; ++fi)
#pragma unroll
        for (int ni = 0; ni < 8; ++ni)
#pragma unroll
            for (int q = 0; q < 4; ++q) acc[fi][ni][q] = 0.f;

    load_stage(0, 0); CP_COMMIT();
    load_stage(1, 1); CP_COMMIT();

    for (int c = 0; c < NCHUNK; ++c) {
        CP_WAIT1();
        __syncthreads();
        uint32_t st = sb + (c & 1) * STAGE_BYTES;
        uint32_t stB = st + A_BYTES;
#pragma unroll
        for (int tap = 0; tap < 3; ++tap) {
            uint32_t stA = st + tap * A_TAP_BYTES;
#pragma unroll
            for (int j = 0; j < 4; ++j) {      // 4 k16 steps per 128B row
                uint32_t a[2][4], bf[4][4];
#pragma unroll
                for (int fi = 0; fi < 2; ++fi) {
                    uint32_t addr = stA + aBase[fi] + ((aK0 + j * 32) ^ aXor[fi]);
                    LDSM_X4(a[fi][0], a[fi][1], a[fi][2], a[fi][3], addr);
                }
#pragma unroll
                for (int half = 0; half < 4; ++half) {
                    int row = bRow[half] + tap;
                    uint32_t addr = stB + row * 128 + ((bK0 + j * 32) ^ ((row & 7) * 16));
                    LDSM_X4(bf[half][0], bf[half][1], bf[half][2], bf[half][3], addr);
                }
#pragma unroll
                for (int fi = 0; fi < 2; ++fi)
#pragma unroll
                    for (int ni = 0; ni < 8; ++ni)
                        mma16816(acc[fi][ni], a[fi][0], a[fi][1], a[fi][2], a[fi][3],
                                 bf[ni >> 1][(ni & 1) * 2], bf[ni >> 1][(ni & 1) * 2 + 1]);
            }
        }
        __syncthreads();
        if (c + 2 < NCHUNK) load_stage(c + 2, c & 1);
        CP_COMMIT();
    }

    // ---- epilogue: fmap bulk-copy to smem + bias/relu fp32 staging + coalesced sweep ----
    __syncthreads();                           // all compute done; safe to reuse stage smem
    float* stile = (float*)smem;               // [64][TS]
    unsigned char* sfmap = (unsigned char*)(smem + TILE_BYTES);   // [SPAN]

    // bulk coalesced fmap copy (overlaps with staging below)
    {
        const unsigned char* gf = g_fmap + ((size_t)b * NPB + (p0 >> 8)) * SPAN;
        for (int i = tid; i < SPAN / 16; i += 256)
            cp_async16(sb + TILE_BYTES + i * 16, gf + i * 16);
        CP_COMMIT();
    }

    // stage tile with bias + relu applied (fp32)
    {
        int hl = wm * 32 + (lane >> 2);
        int pl = wn * 64 + (lane & 3) * 2;
#pragma unroll
        for (int fi = 0; fi < 2; ++fi)
#pragma unroll
            for (int rr = 0; rr < 2; ++rr) {
                int hh = hl + fi * 16 + rr * 8;
                float cc = g_c2[h0 + hh];
#pragma unroll
                for (int ni = 0; ni < 8; ++ni) {
                    float2 v;
                    v.x = fmaxf(acc[fi][ni][rr * 2 + 0] + cc, 0.f);
                    v.y = fmaxf(acc[fi][ni][rr * 2 + 1] + cc, 0.f);
                    *(float2*)&stile[hh * TS + pl + ni * 8] = v;
                }
            }
    }

    bool lastblk = (p0 + TN >= PDIM);
    int fs = g_sd[b * PDIM + p0].x;
    int fe = lastblk ? g_total[b] : g_sd[b * PDIM + p0 + TN].x;
    int L = fe - fs;
    int Lw = lastblk ? (F - fs) : L;           // last block also zeroes the masked tail
    CP_WAIT0();
    __syncthreads();

    for (int h = wid; h < TM; h += 8) {
        float* orow = out + ((size_t)b * HDIM + h0 + h) * F + fs;
        const float* srow = stile + h * TS;
        for (int f = lane; f < Lw; f += 32)
            orow[f] = (f < L) ? srow[sfmap[f]] : 0.f;
    }
}

// ---------------- launch ----------------
extern "C" void kernel_launch(void* const* d_in, const int* in_sizes, int n_in,
                              void* d_out, int out_size) {
    const int* ids   = (const int*)d_in[0];
    const int* durs  = (const int*)d_in[1];
    const float* emb = (const float*)d_in[2];
    const float* w1  = (const float*)d_in[3];
    const float* b1  = (const float*)d_in[4];
    const float* g1  = (const float*)d_in[5];
    const float* be1 = (const float*)d_in[6];
    const float* m1  = (const float*)d_in[7];
    const float* v1  = (const float*)d_in[8];
    const float* w2  = (const float*)d_in[9];
    const float* b2  = (const float*)d_in[10];
    const float* g2  = (const float*)d_in[11];
    const float* be2 = (const float*)d_in[12];
    const float* m2  = (const float*)d_in[13];
    const float* v2  = (const float*)d_in[14];
    float* out = (float*)d_out;
    int F = out_size / (BDIM * HDIM);

    cudaFuncSetAttribute(k_gemm, cudaFuncAttributeMaxDynamicSharedMemorySize, GEMM_SMEM);

    k_prep<<<3072 + 64, 256>>>(w1, b1, g1, be1, m1, v1, b2, g2, be2, m2, v2);   // launch 0
    k_tab<<<300 + 768 + 32, 512>>>(emb, g1, v1, w2, g2, v2, durs);              // launch 1
    k_y1<<<dim3(BDIM, PDIM / 16), 256>>>(ids);                                  // launch 2
    k_gemm<<<dim3(PDIM / TN, HDIM / TM, BDIM), 256, GEMM_SMEM>>>(out, F);       // launch 3 (profiled)
}

// round 13
// speedup vs baseline: 1.7682x; 1.0130x over previous
#include <cuda_runtime.h>
#include <cuda_fp16.h>
#include <cstdint>

#define BDIM 32
#define PDIM 1024
#define VDIM 100
#define EDIM 512
#define HDIM 512
#define EPSV 1e-5f
#define PPAD (PDIM + 2)

// GEMM tiling: CTA 64x256, fp16 mma.sync, shared-B across taps, 2-stage, 2 CTA/SM
#define TM 64
#define TN 256
#define TKH 64                             // K elems (fp16) per chunk = 128B rows
#define NCHUNK (HDIM / TKH)                // 8
#define A_TAP_BYTES (TM * 128)             // 8192 per tap
#define A_BYTES (3 * A_TAP_BYTES)          // 24576
#define B_ROWS_PAD 260                     // 256 + 2 halo, padded
#define B_BYTES (B_ROWS_PAD * 128)         // 33280
#define STAGE_BYTES (A_BYTES + B_BYTES)    // 57856
#define GEMM_SMEM (2 * STAGE_BYTES)        // 115712  (2 CTAs = 226 KB/SM)
#define STAGE_CHUNKS (STAGE_BYTES / 16)    // 3616
#define A_CHUNKS (A_BYTES / 16)            // 1536
// epilogue smem reuse: fp32 post-bias tile 64 x 258 floats + fmap bytes
#define TS 258
#define TILE_BYTES (TM * TS * 4)           // 66048
#define NPB (PDIM / TN)                    // 4 p-blocks per batch
#define SPAN 2304                          // max frames per p-block (256 * 9)

// ---------------- scratch (static device globals) ----------------
__device__ float  g_W1t[3 * EDIM * HDIM];            // [k][e][h]
__device__ __half g_Atab[3 * VDIM * HDIM];           // [k][v][h] fp16
__device__ float  g_c1[HDIM];
__device__ float  g_c2[HDIM];
__device__ __half g_W2k[3 * HDIM * HDIM];            // [tap][h][h'] fp16, K-major
__device__ __half g_y1t[(size_t)BDIM * PPAD * HDIM]; // [b][p+1][h'] fp16, halo rows zero
__device__ int2   g_sd[BDIM * PDIM];                 // per-phoneme (start, dur)
__device__ int    g_total[BDIM];                     // per-batch total frames
__device__ unsigned char g_fmap[BDIM * NPB * SPAN];  // frame -> tile-local phoneme idx

// ---------------- PTX helpers (base ISA only) ----------------
__device__ __forceinline__ uint32_t smem_u32(const void* p) {
    uint32_t a;
    asm("{ .reg .u64 t; cvta.to.shared.u64 t, %1; cvt.u32.u64 %0, t; }" : "=r"(a) : "l"(p));
    return a;
}
__device__ __forceinline__ void cp_async16(uint32_t s, const void* g) {
    asm volatile("cp.async.cg.shared.global [%0], [%1], 16;" :: "r"(s), "l"(g) : "memory");
}
#define CP_COMMIT() asm volatile("cp.async.commit_group;" ::: "memory")
#define CP_WAIT1()  asm volatile("cp.async.wait_group 1;" ::: "memory")
#define CP_WAIT0()  asm volatile("cp.async.wait_group 0;" ::: "memory")

#define LDSM_X4(r0, r1, r2, r3, addr)                                        \
    asm volatile("ldmatrix.sync.aligned.m8n8.x4.shared.b16 {%0,%1,%2,%3}, [%4];" \
        : "=r"(r0), "=r"(r1), "=r"(r2), "=r"(r3) : "r"(addr))

__device__ __forceinline__ void mma16816(float* d, uint32_t a0, uint32_t a1,
                                         uint32_t a2, uint32_t a3,
                                         uint32_t b0, uint32_t b1) {
    asm volatile(
        "mma.sync.aligned.m16n8k16.row.col.f32.f16.f16.f32 "
        "{%0,%1,%2,%3}, {%4,%5,%6,%7}, {%8,%9}, {%0,%1,%2,%3};"
        : "+f"(d[0]), "+f"(d[1]), "+f"(d[2]), "+f"(d[3])
        : "r"(a0), "r"(a1), "r"(a2), "r"(a3), "r"(b0), "r"(b1));
}

__device__ __forceinline__ uint32_t sw128(uint32_t off) { return off ^ ((off >> 3) & 0x70); }

// ---------------- launch 0: fold-BN vectors + W1 transpose + y1t halo zero ----------------
__global__ void k_prep(const float* __restrict__ w1,
                       const float* b1, const float* g1, const float* be1,
                       const float* m1, const float* v1,
                       const float* b2, const float* g2, const float* be2,
                       const float* m2, const float* v2) {
    int bx = blockIdx.x, tid = threadIdx.x;
    if (bx < 3072) {
        // W1 transpose (H,E,3) -> [k][e][h]
        int idx = bx * 256 + tid;
        int h = idx / (EDIM * 3);
        int r = idx % (EDIM * 3);
        int e = r / 3;
        int k = r % 3;
        g_W1t[(k * EDIM + e) * HDIM + h] = w1[idx];
    } else {
        int zb = bx - 3072;                 // 0..63: zero halo rows of y1t (as uint32 words)
        int i = zb * 256 + tid;             // 16384 words = 32 b * 2 rows * 256 words
        int b = i / 512;
        int r = i % 512;
        int p = (r < 256) ? 0 : (PPAD - 1);
        int hw = r % 256;
        ((uint32_t*)g_y1t)[((size_t)b * PPAD + p) * (HDIM / 2) + hw] = 0u;
        if (zb == 0) {
#pragma unroll
            for (int q = 0; q < 2; ++q) {
                int hh = tid + q * 256;
                float s1 = g1[hh] * rsqrtf(v1[hh] + EPSV);
                g_c1[hh] = b1[hh] * s1 + be1[hh] - m1[hh] * s1;
                float s2 = g2[hh] * rsqrtf(v2[hh] + EPSV);
                g_c2[hh] = b2[hh] * s2 + be2[hh] - m2[hh] * s2;
            }
        }
    }
}

// ---------------- launch 1: Atab (tiled mini-GEMM) + W2k(fp16) + scan + fmap ----------------
__global__ void k_tab(const float* __restrict__ emb,
                      const float* __restrict__ g1, const float* __restrict__ v1,
                      const float* __restrict__ w2,
                      const float* __restrict__ g2, const float* __restrict__ v2,
                      const int* __restrict__ durs) {
    __shared__ float es[EDIM];          // also scan scratch (as int)
    __shared__ int bstart[NPB];
    __shared__ float W1s[64 * 32];      // [e-tile][h-tile]
    __shared__ float embs[112 * 64];    // [v(padded)][e-tile]
    int bx = blockIdx.x, tid = threadIdx.x;   // 512 threads
    if (bx < 48) {
        // Atab[k][v][h] = scale1[h]*(emb[v] . W1t[k][:,h]); W1t read ONCE total.
        int k = bx >> 4, ht = bx & 15;
        int h = tid & 31, vg = tid >> 5;       // 16 v-groups
        float acc[7] = {0.f, 0.f, 0.f, 0.f, 0.f, 0.f, 0.f};
        for (int et = 0; et < 8; ++et) {
            int e0 = et * 64;
#pragma unroll
            for (int j = 0; j < 4; ++j) {      // W1s: 64 x 32
                int idx = tid + j * 512;
                int e = idx >> 5, hh = idx & 31;
                W1s[idx] = g_W1t[((size_t)k * EDIM + e0 + e) * HDIM + ht * 32 + hh];
            }
#pragma unroll
            for (int j = 0; j < 14; ++j) {     // embs: 112 x 64 (zero-fill v>=100)
                int idx = tid + j * 512;
                if (idx < 112 * 64) {
                    int v = idx >> 6, e = idx & 63;
                    embs[idx] = (v < VDIM) ? emb[v * EDIM + e0 + e] : 0.f;
                }
            }
            __syncthreads();
#pragma unroll
            for (int e = 0; e < 64; ++e) {
                float w = W1s[e * 32 + h];
#pragma unroll
                for (int j = 0; j < 7; ++j)
                    acc[j] += embs[(vg + 16 * j) * 64 + e] * w;
            }
            __syncthreads();
        }
        int gh = ht * 32 + h;
        float scale = g1[gh] * rsqrtf(v1[gh] + EPSV);
#pragma unroll
        for (int j = 0; j < 7; ++j) {
            int v = vg + 16 * j;
            if (v < VDIM)
                g_Atab[((size_t)k * VDIM + v) * HDIM + gh] = __float2half(acc[j] * scale);
        }
    } else if (bx < 816) {
        // W2k[tap][h][hp] = fp16(scale2[h]*W2[h,hp,tap]), packed pairs
        int pidx = (bx - 48) * 512 + tid;        // over 3*512*256 half2 pairs
        int tap = pidx / (HDIM * (HDIM / 2));
        int r = pidx % (HDIM * (HDIM / 2));
        int h = r / (HDIM / 2);
        int hp = (r % (HDIM / 2)) * 2;
        float s2 = g2[h] * rsqrtf(v2[h] + EPSV);
        float v0 = w2[h * HDIM * 3 + hp * 3 + tap] * s2;
        float v1f = w2[h * HDIM * 3 + (hp + 1) * 3 + tap] * s2;
        ((half2*)g_W2k)[pidx] = __floats2half2_rn(v0, v1f);
    } else {
        // duration scan for batch b: (start, dur) per phoneme + total + fmap bytes
        int b = bx - 816;                        // 0..31
        int* ps = (int*)es;
        int d0 = durs[b * PDIM + 2 * tid];
        int d1 = durs[b * PDIM + 2 * tid + 1];
        ps[tid] = d0 + d1;
        __syncthreads();
        for (int off = 1; off < 512; off <<= 1) {
            int t = (tid >= off) ? ps[tid - off] : 0;
            __syncthreads();
            ps[tid] += t;
            __syncthreads();
        }
        int incl = ps[tid];
        int excl = incl - d0 - d1;
        g_sd[b * PDIM + 2 * tid]     = make_int2(excl, d0);
        g_sd[b * PDIM + 2 * tid + 1] = make_int2(excl + d0, d1);
        if (tid == 511) g_total[b] = incl;
        if (tid < NPB) bstart[tid] = (tid == 0) ? 0 : ps[tid * (TN / 2) - 1];
        __syncthreads();
        // fmap: tile-local phoneme index per frame (both phonemes in same p-block)
        int p_ = 2 * tid;
        int pb = p_ >> 8;
        unsigned char* fm = g_fmap + (b * NPB + pb) * SPAN;
        int rel = excl - bstart[pb];
        for (int i = 0; i < d0; ++i) fm[rel + i] = (unsigned char)(p_ & 255);
        rel += d0;
        for (int i = 0; i < d1; ++i) fm[rel + i] = (unsigned char)((p_ + 1) & 255);
    }
}

// ---------------- launch 2: y1 table lookups (fp16 Atab) -> transposed, padded, fp16 ----------------
__global__ void k_y1(const int* __restrict__ ids) {
    __shared__ int sid[18];
    int b = blockIdx.x;
    int p0 = blockIdx.y * 16;
    int tid = threadIdx.x;   // 256
    if (tid < 18) {
        int q = p0 - 1 + tid;
        sid[tid] = (q >= 0 && q < PDIM) ? ids[b * PDIM + q] : -1;
    }
    __syncthreads();
    int h = tid * 2;                       // each thread: one half2 pair
    float c0 = g_c1[h], c1 = g_c1[h + 1];
    const half2* atab = (const half2*)g_Atab;
    half2* out = (half2*)g_y1t;
#pragma unroll
    for (int pl = 0; pl < 16; ++pl) {
        int i0 = sid[pl], i1 = sid[pl + 1], i2 = sid[pl + 2];
        float v0 = c0, v1 = c1;
        if (i0 >= 0) {
            float2 f = __half22float2(atab[(0 * VDIM + i0) * (HDIM / 2) + tid]);
            v0 += f.x; v1 += f.y;
        }
        if (i1 >= 0) {
            float2 f = __half22float2(atab[(1 * VDIM + i1) * (HDIM / 2) + tid]);
            v0 += f.x; v1 += f.y;
        }
        if (i2 >= 0) {
            float2 f = __half22float2(atab[(2 * VDIM + i2) * (HDIM / 2) + tid]);
            v0 += f.x; v1 += f.y;
        }
        v0 = fmaxf(v0, 0.f);
        v1 = fmaxf(v1, 0.f);
        out[((size_t)b * PPAD + p0 + pl + 1) * (HDIM / 2) + tid] = __floats2half2_rn(v0, v1);
    }
}

// ---------------- launch 3: conv2 GEMM + fp32-staged coalesced upsample epilogue ----------------
__global__ __launch_bounds__(256, 2) void k_gemm(float* __restrict__ out, int F) {
    extern __shared__ __align__(1024) char smem[];
    uint32_t sb = smem_u32(smem);
    int tid = threadIdx.x;
    int lane = tid & 31, wid = tid >> 5;   // 8 warps
    int wm = wid & 1;          // 2 m-tiles of 32
    int wn = wid >> 1;         // 4 n-tiles of 64
    int p0 = blockIdx.x * TN;
    int h0 = blockIdx.y * TM;
    int b = blockIdx.z;

    // ---- per-lane ldmatrix address components (128B K-major rows, SW128) ----
    uint32_t aBase[2], aXor[2];
#pragma unroll
    for (int fi = 0; fi < 2; ++fi) {
        int row = wm * 32 + fi * 16 + (lane & 15);
        aBase[fi] = row * 128;
        aXor[fi] = (row & 7) * 16;
    }
    uint32_t aK0 = (lane >> 4) * 16;

    int nb = (lane & 7) | ((lane & 16) >> 1);
    uint32_t bK0 = ((lane >> 3) & 1) * 16;
    int bRow[4];
#pragma unroll
    for (int half = 0; half < 4; ++half)
        bRow[half] = wn * 64 + half * 16 + nb;

    // ---- stage loader: 3 A tap tiles (64 rows each) + shared B halo tile ----
    auto load_stage = [&](int c, int s) {
        int kk = c * TKH;
        uint32_t st = sb + s * STAGE_BYTES;
#pragma unroll
        for (int j = 0; j < 15; ++j) {
            int i = tid + j * 256;
            if (i >= STAGE_CHUNKS) break;
            if (i < A_CHUNKS) {                // A: 3 tap tiles, 64 rows x 128B
                int tap = i >> 9;
                int r = i & 511;
                int row = r >> 3, seg = r & 7;
                const __half* g = g_W2k + ((size_t)tap * HDIM + h0 + row) * HDIM + kk + seg * 8;
                cp_async16(st + tap * A_TAP_BYTES + sw128((uint32_t)(row * 128 + seg * 16)), g);
            } else {                           // B: halo rows p0-1 .. p0+256 (+pad clamp)
                int ii = i - A_CHUNKS;
                int row = ii >> 3, seg = ii & 7;
                int rowc = row < 258 ? row : 257;
                const __half* g = g_y1t + ((size_t)b * PPAD + p0 + rowc) * HDIM + kk + seg * 8;
                cp_async16(st + A_BYTES + sw128((uint32_t)(row * 128 + seg * 16)), g);
            }
        }
    };

    float acc[2][8][4];
#pragma unroll
    for (int fi = 0; fi < 2; ++fi)
#pragma unroll
        for (int ni = 0; ni < 8; ++ni)
#pragma unroll
            for (int q = 0; q < 4; ++q) acc[fi][ni][q] = 0.f;

    load_stage(0, 0); CP_COMMIT();
    load_stage(1, 1); CP_COMMIT();

    for (int c = 0; c < NCHUNK; ++c) {
        CP_WAIT1();
        __syncthreads();
        uint32_t st = sb + (c & 1) * STAGE_BYTES;
        uint32_t stB = st + A_BYTES;
#pragma unroll
        for (int tap = 0; tap < 3; ++tap) {
            uint32_t stA = st + tap * A_TAP_BYTES;
#pragma unroll
            for (int j = 0; j < 4; ++j) {      // 4 k16 steps per 128B row
                uint32_t a[2][4], bf[4][4];
#pragma unroll
                for (int fi = 0; fi < 2; ++fi) {
                    uint32_t addr = stA + aBase[fi] + ((aK0 + j * 32) ^ aXor[fi]);
                    LDSM_X4(a[fi][0], a[fi][1], a[fi][2], a[fi][3], addr);
                }
#pragma unroll
                for (int half = 0; half < 4; ++half) {
                    int row = bRow[half] + tap;
                    uint32_t addr = stB + row * 128 + ((bK0 + j * 32) ^ ((row & 7) * 16));
                    LDSM_X4(bf[half][0], bf[half][1], bf[half][2], bf[half][3], addr);
                }
#pragma unroll
                for (int fi = 0; fi < 2; ++fi)
#pragma unroll
                    for (int ni = 0; ni < 8; ++ni)
                        mma16816(acc[fi][ni], a[fi][0], a[fi][1], a[fi][2], a[fi][3],
                                 bf[ni >> 1][(ni & 1) * 2], bf[ni >> 1][(ni & 1) * 2 + 1]);
            }
        }
        __syncthreads();
        if (c + 2 < NCHUNK) load_stage(c + 2, c & 1);
        CP_COMMIT();
    }

    // ---- epilogue: fmap bulk-copy to smem + bias/relu fp32 staging + coalesced sweep ----
    __syncthreads();                           // all compute done; safe to reuse stage smem
    float* stile = (float*)smem;               // [64][TS]
    unsigned char* sfmap = (unsigned char*)(smem + TILE_BYTES);   // [SPAN]

    // bulk coalesced fmap copy (overlaps with staging below)
    {
        const unsigned char* gf = g_fmap + ((size_t)b * NPB + (p0 >> 8)) * SPAN;
        for (int i = tid; i < SPAN / 16; i += 256)
            cp_async16(sb + TILE_BYTES + i * 16, gf + i * 16);
        CP_COMMIT();
    }

    // stage tile with bias + relu applied (fp32)
    {
        int hl = wm * 32 + (lane >> 2);
        int pl = wn * 64 + (lane & 3) * 2;
#pragma unroll
        for (int fi = 0; fi < 2; ++fi)
#pragma unroll
            for (int rr = 0; rr < 2; ++rr) {
                int hh = hl + fi * 16 + rr * 8;
                float cc = g_c2[h0 + hh];
#pragma unroll
                for (int ni = 0; ni < 8; ++ni) {
                    float2 v;
                    v.x = fmaxf(acc[fi][ni][rr * 2 + 0] + cc, 0.f);
                    v.y = fmaxf(acc[fi][ni][rr * 2 + 1] + cc, 0.f);
                    *(float2*)&stile[hh * TS + pl + ni * 8] = v;
                }
            }
    }

    bool lastblk = (p0 + TN >= PDIM);
    int fs = g_sd[b * PDIM + p0].x;
    int fe = lastblk ? g_total[b] : g_sd[b * PDIM + p0 + TN].x;
    int L = fe - fs;
    int Lw = lastblk ? (F - fs) : L;           // last block also zeroes the masked tail
    CP_WAIT0();
    __syncthreads();

    for (int h = wid; h < TM; h += 8) {
        float* orow = out + ((size_t)b * HDIM + h0 + h) * F + fs;
        const float* srow = stile + h * TS;
        for (int f = lane; f < Lw; f += 32)
            orow[f] = (f < L) ? srow[sfmap[f]] : 0.f;
    }
}

// ---------------- launch ----------------
extern "C" void kernel_launch(void* const* d_in, const int* in_sizes, int n_in,
                              void* d_out, int out_size) {
    const int* ids   = (const int*)d_in[0];
    const int* durs  = (const int*)d_in[1];
    const float* emb = (const float*)d_in[2];
    const float* w1  = (const float*)d_in[3];
    const float* b1  = (const float*)d_in[4];
    const float* g1  = (const float*)d_in[5];
    const float* be1 = (const float*)d_in[6];
    const float* m1  = (const float*)d_in[7];
    const float* v1  = (const float*)d_in[8];
    const float* w2  = (const float*)d_in[9];
    const float* b2  = (const float*)d_in[10];
    const float* g2  = (const float*)d_in[11];
    const float* be2 = (const float*)d_in[12];
    const float* m2  = (const float*)d_in[13];
    const float* v2  = (const float*)d_in[14];
    float* out = (float*)d_out;
    int F = out_size / (BDIM * HDIM);

    cudaFuncSetAttribute(k_gemm, cudaFuncAttributeMaxDynamicSharedMemorySize, GEMM_SMEM);

    k_prep<<<3072 + 64, 256>>>(w1, b1, g1, be1, m1, v1, b2, g2, be2, m2, v2);   // launch 0
    k_tab<<<48 + 768 + 32, 512>>>(emb, g1, v1, w2, g2, v2, durs);               // launch 1
    k_y1<<<dim3(BDIM, PDIM / 16), 256>>>(ids);                                  // launch 2
    k_gemm<<<dim3(PDIM / TN, HDIM / TM, BDIM), 256, GEMM_SMEM>>>(out, F);       // launch 3 (profiled)
}

// round 14
// speedup vs baseline: 1.8519x; 1.0473x over previous
#include <cuda_runtime.h>
#include <cuda_fp16.h>
#include <cstdint>

#define BDIM 32
#define PDIM 1024
#define VDIM 100
#define EDIM 512
#define HDIM 512
#define EPSV 1e-5f
#define PPAD (PDIM + 2)

// GEMM tiling: CTA 64x256, fp16 mma.sync, shared-B across taps, 2-stage, 2 CTA/SM
#define TM 64
#define TN 256
#define TKH 64                             // K elems (fp16) per chunk = 128B rows
#define NCHUNK (HDIM / TKH)                // 8
#define A_TAP_BYTES (TM * 128)             // 8192 per tap
#define A_BYTES (3 * A_TAP_BYTES)          // 24576
#define B_ROWS_PAD 260                     // 256 + 2 halo, padded
#define B_BYTES (B_ROWS_PAD * 128)         // 33280
#define STAGE_BYTES (A_BYTES + B_BYTES)    // 57856
#define GEMM_SMEM (2 * STAGE_BYTES)        // 115712  (2 CTAs = 226 KB/SM)
#define STAGE_CHUNKS (STAGE_BYTES / 16)    // 3616
#define A_CHUNKS (A_BYTES / 16)            // 1536
// epilogue smem reuse: fp32 post-bias tile 64 x 258 floats + fmap bytes
#define TS 258
#define TILE_BYTES (TM * TS * 4)           // 66048
#define NPB (PDIM / TN)                    // 4 p-blocks per batch
#define SPAN 2304                          // max frames per p-block (256 * 9)

// ---------------- scratch (static device globals) ----------------
__device__ __half g_Atab[3 * VDIM * HDIM];           // [k][v][h] fp16
__device__ float  g_c1[HDIM];
__device__ float  g_c2[HDIM];
__device__ __half g_W2k[3 * HDIM * HDIM];            // [tap][h][h'] fp16, K-major
__device__ __half g_y1t[(size_t)BDIM * PPAD * HDIM]; // [b][p+1][h'] fp16, halo rows zero
__device__ int2   g_sd[BDIM * PDIM];                 // per-phoneme (start, dur)
__device__ int    g_total[BDIM];                     // per-batch total frames
__device__ unsigned char g_fmap[BDIM * NPB * SPAN];  // frame -> tile-local phoneme idx

// ---------------- PTX helpers (base ISA only) ----------------
__device__ __forceinline__ uint32_t smem_u32(const void* p) {
    uint32_t a;
    asm("{ .reg .u64 t; cvta.to.shared.u64 t, %1; cvt.u32.u64 %0, t; }" : "=r"(a) : "l"(p));
    return a;
}
__device__ __forceinline__ void cp_async16(uint32_t s, const void* g) {
    asm volatile("cp.async.cg.shared.global [%0], [%1], 16;" :: "r"(s), "l"(g) : "memory");
}
#define CP_COMMIT() asm volatile("cp.async.commit_group;" ::: "memory")
#define CP_WAIT1()  asm volatile("cp.async.wait_group 1;" ::: "memory")
#define CP_WAIT0()  asm volatile("cp.async.wait_group 0;" ::: "memory")

#define LDSM_X4(r0, r1, r2, r3, addr)                                        \
    asm volatile("ldmatrix.sync.aligned.m8n8.x4.shared.b16 {%0,%1,%2,%3}, [%4];" \
        : "=r"(r0), "=r"(r1), "=r"(r2), "=r"(r3) : "r"(addr))

__device__ __forceinline__ void mma16816(float* d, uint32_t a0, uint32_t a1,
                                         uint32_t a2, uint32_t a3,
                                         uint32_t b0, uint32_t b1) {
    asm volatile(
        "mma.sync.aligned.m16n8k16.row.col.f32.f16.f16.f32 "
        "{%0,%1,%2,%3}, {%4,%5,%6,%7}, {%8,%9}, {%0,%1,%2,%3};"
        : "+f"(d[0]), "+f"(d[1]), "+f"(d[2]), "+f"(d[3])
        : "r"(a0), "r"(a1), "r"(a2), "r"(a3), "r"(b0), "r"(b1));
}

__device__ __forceinline__ uint32_t sw128(uint32_t off) { return off ^ ((off >> 3) & 0x70); }

// ---------------- launch 0: Atab (direct-from-w1 mini-GEMM) + W2k + scan/fmap + vecs ----------------
__global__ void k_tab(const float* __restrict__ emb,
                      const float* __restrict__ w1,
                      const float* __restrict__ b1, const float* __restrict__ g1,
                      const float* __restrict__ be1, const float* __restrict__ m1,
                      const float* __restrict__ v1,
                      const float* __restrict__ w2,
                      const float* __restrict__ b2, const float* __restrict__ g2,
                      const float* __restrict__ be2, const float* __restrict__ m2,
                      const float* __restrict__ v2,
                      const int* __restrict__ durs) {
    __shared__ float es[EDIM];          // scan scratch (as int)
    __shared__ int bstart[NPB];
    __shared__ float W1s[64 * 33];      // [e-tile][h-tile], pitch 33 (conflict-free)
    __shared__ float embs[112 * 64];    // [v(padded)][e-tile]
    int bx = blockIdx.x, tid = threadIdx.x;   // 512 threads
    if (bx < 48) {
        // Atab[k][v][h] = scale1[h]*(emb[v] . w1[h,:,k]); w1 read directly (e-fastest)
        int k = bx >> 4, ht = bx & 15;
        int h = tid & 31, vg = tid >> 5;       // 16 v-groups
        float acc[7] = {0.f, 0.f, 0.f, 0.f, 0.f, 0.f, 0.f};
        for (int et = 0; et < 8; ++et) {
            int e0 = et * 64;
#pragma unroll
            for (int j = 0; j < 4; ++j) {      // W1s: 64 e x 32 hh, e fastest in tid
                int idx = tid + j * 512;
                int e = idx & 63, hh = idx >> 6;
                W1s[e * 33 + hh] = w1[(size_t)(ht * 32 + hh) * (EDIM * 3) + (e0 + e) * 3 + k];
            }
#pragma unroll
            for (int j = 0; j < 14; ++j) {     // embs: 112 x 64 (zero-fill v>=100)
                int idx = tid + j * 512;
                if (idx < 112 * 64) {
                    int v = idx >> 6, e = idx & 63;
                    embs[idx] = (v < VDIM) ? emb[v * EDIM + e0 + e] : 0.f;
                }
            }
            __syncthreads();
#pragma unroll
            for (int e = 0; e < 64; ++e) {
                float w = W1s[e * 33 + h];
#pragma unroll
                for (int j = 0; j < 7; ++j)
                    acc[j] += embs[(vg + 16 * j) * 64 + e] * w;
            }
            __syncthreads();
        }
        int gh = ht * 32 + h;
        float scale = g1[gh] * rsqrtf(v1[gh] + EPSV);
#pragma unroll
        for (int j = 0; j < 7; ++j) {
            int v = vg + 16 * j;
            if (v < VDIM)
                g_Atab[((size_t)k * VDIM + v) * HDIM + gh] = __float2half(acc[j] * scale);
        }
    } else if (bx < 816) {
        // W2k[tap][h][hp] = fp16(scale2[h]*W2[h,hp,tap]), packed pairs
        int pidx = (bx - 48) * 512 + tid;        // over 3*512*256 half2 pairs
        int tap = pidx / (HDIM * (HDIM / 2));
        int r = pidx % (HDIM * (HDIM / 2));
        int h = r / (HDIM / 2);
        int hp = (r % (HDIM / 2)) * 2;
        float s2 = g2[h] * rsqrtf(v2[h] + EPSV);
        float v0 = w2[h * HDIM * 3 + hp * 3 + tap] * s2;
        float v1f = w2[h * HDIM * 3 + (hp + 1) * 3 + tap] * s2;
        ((half2*)g_W2k)[pidx] = __floats2half2_rn(v0, v1f);
    } else if (bx < 848) {
        // duration scan for batch b: (start, dur) per phoneme + total + fmap bytes
        int b = bx - 816;                        // 0..31
        int* ps = (int*)es;
        int d0 = durs[b * PDIM + 2 * tid];
        int d1 = durs[b * PDIM + 2 * tid + 1];
        ps[tid] = d0 + d1;
        __syncthreads();
        for (int off = 1; off < 512; off <<= 1) {
            int t = (tid >= off) ? ps[tid - off] : 0;
            __syncthreads();
            ps[tid] += t;
            __syncthreads();
        }
        int incl = ps[tid];
        int excl = incl - d0 - d1;
        g_sd[b * PDIM + 2 * tid]     = make_int2(excl, d0);
        g_sd[b * PDIM + 2 * tid + 1] = make_int2(excl + d0, d1);
        if (tid == 511) g_total[b] = incl;
        if (tid < NPB) bstart[tid] = (tid == 0) ? 0 : ps[tid * (TN / 2) - 1];
        __syncthreads();
        // fmap: tile-local phoneme index per frame (both phonemes in same p-block)
        int p_ = 2 * tid;
        int pb = p_ >> 8;
        unsigned char* fm = g_fmap + (b * NPB + pb) * SPAN;
        int rel = excl - bstart[pb];
        for (int i = 0; i < d0; ++i) fm[rel + i] = (unsigned char)(p_ & 255);
        rel += d0;
        for (int i = 0; i < d1; ++i) fm[rel + i] = (unsigned char)((p_ + 1) & 255);
    } else {
        // fold-BN bias vectors (1 block, 512 threads = HDIM)
        int h = tid;
        float s1 = g1[h] * rsqrtf(v1[h] + EPSV);
        g_c1[h] = b1[h] * s1 + be1[h] - m1[h] * s1;
        float s2 = g2[h] * rsqrtf(v2[h] + EPSV);
        g_c2[h] = b2[h] * s2 + be2[h] - m2[h] * s2;
    }
}

// ---------------- launch 1: y1 table lookups (fp16 Atab) -> transposed, padded, fp16 ----------------
__global__ void k_y1(const int* __restrict__ ids) {
    __shared__ int sid[18];
    int b = blockIdx.x;
    int p0 = blockIdx.y * 16;
    int tid = threadIdx.x;   // 256
    half2* out = (half2*)g_y1t;
    // edge blocks zero the halo rows (256 half2 words each)
    if (blockIdx.y == 0)
        out[((size_t)b * PPAD + 0) * (HDIM / 2) + tid] = __floats2half2_rn(0.f, 0.f);
    if (blockIdx.y == (PDIM / 16) - 1)
        out[((size_t)b * PPAD + PPAD - 1) * (HDIM / 2) + tid] = __floats2half2_rn(0.f, 0.f);
    if (tid < 18) {
        int q = p0 - 1 + tid;
        sid[tid] = (q >= 0 && q < PDIM) ? ids[b * PDIM + q] : -1;
    }
    __syncthreads();
    int h = tid * 2;                       // each thread: one half2 pair
    float c0 = g_c1[h], c1 = g_c1[h + 1];
    const half2* atab = (const half2*)g_Atab;
#pragma unroll
    for (int pl = 0; pl < 16; ++pl) {
        int i0 = sid[pl], i1 = sid[pl + 1], i2 = sid[pl + 2];
        float v0 = c0, v1 = c1;
        if (i0 >= 0) {
            float2 f = __half22float2(atab[(0 * VDIM + i0) * (HDIM / 2) + tid]);
            v0 += f.x; v1 += f.y;
        }
        if (i1 >= 0) {
            float2 f = __half22float2(atab[(1 * VDIM + i1) * (HDIM / 2) + tid]);
            v0 += f.x; v1 += f.y;
        }
        if (i2 >= 0) {
            float2 f = __half22float2(atab[(2 * VDIM + i2) * (HDIM / 2) + tid]);
            v0 += f.x; v1 += f.y;
        }
        v0 = fmaxf(v0, 0.f);
        v1 = fmaxf(v1, 0.f);
        out[((size_t)b * PPAD + p0 + pl + 1) * (HDIM / 2) + tid] = __floats2half2_rn(v0, v1);
    }
}

// ---------------- launch 2: conv2 GEMM + fp32-staged coalesced upsample epilogue ----------------
__global__ __launch_bounds__(256, 2) void k_gemm(float* __restrict__ out, int F) {
    extern __shared__ __align__(1024) char smem[];
    uint32_t sb = smem_u32(smem);
    int tid = threadIdx.x;
    int lane = tid & 31, wid = tid >> 5;   // 8 warps
    int wm = wid & 1;          // 2 m-tiles of 32
    int wn = wid >> 1;         // 4 n-tiles of 64
    int p0 = blockIdx.x * TN;
    int h0 = blockIdx.y * TM;
    int b = blockIdx.z;

    // ---- per-lane ldmatrix address components (128B K-major rows, SW128) ----
    uint32_t aBase[2], aXor[2];
#pragma unroll
    for (int fi = 0; fi < 2; ++fi) {
        int row = wm * 32 + fi * 16 + (lane & 15);
        aBase[fi] = row * 128;
        aXor[fi] = (row & 7) * 16;
    }
    uint32_t aK0 = (lane >> 4) * 16;

    int nb = (lane & 7) | ((lane & 16) >> 1);
    uint32_t bK0 = ((lane >> 3) & 1) * 16;
    int bRow[4];
#pragma unroll
    for (int half = 0; half < 4; ++half)
        bRow[half] = wn * 64 + half * 16 + nb;

    // ---- stage loader: 3 A tap tiles (64 rows each) + shared B halo tile ----
    auto load_stage = [&](int c, int s) {
        int kk = c * TKH;
        uint32_t st = sb + s * STAGE_BYTES;
#pragma unroll
        for (int j = 0; j < 15; ++j) {
            int i = tid + j * 256;
            if (i >= STAGE_CHUNKS) break;
            if (i < A_CHUNKS) {                // A: 3 tap tiles, 64 rows x 128B
                int tap = i >> 9;
                int r = i & 511;
                int row = r >> 3, seg = r & 7;
                const __half* g = g_W2k + ((size_t)tap * HDIM + h0 + row) * HDIM + kk + seg * 8;
                cp_async16(st + tap * A_TAP_BYTES + sw128((uint32_t)(row * 128 + seg * 16)), g);
            } else {                           // B: halo rows p0-1 .. p0+256 (+pad clamp)
                int ii = i - A_CHUNKS;
                int row = ii >> 3, seg = ii & 7;
                int rowc = row < 258 ? row : 257;
                const __half* g = g_y1t + ((size_t)b * PPAD + p0 + rowc) * HDIM + kk + seg * 8;
                cp_async16(st + A_BYTES + sw128((uint32_t)(row * 128 + seg * 16)), g);
            }
        }
    };

    float acc[2][8][4];
#pragma unroll
    for (int fi = 0; fi < 2; ++fi)
#pragma unroll
        for (int ni = 0; ni < 8; ++ni)
#pragma unroll
            for (int q = 0; q < 4; ++q) acc[fi][ni][q] = 0.f;

    load_stage(0, 0); CP_COMMIT();
    load_stage(1, 1); CP_COMMIT();

    for (int c = 0; c < NCHUNK; ++c) {
        CP_WAIT1();
        __syncthreads();
        uint32_t st = sb + (c & 1) * STAGE_BYTES;
        uint32_t stB = st + A_BYTES;
#pragma unroll
        for (int tap = 0; tap < 3; ++tap) {
            uint32_t stA = st + tap * A_TAP_BYTES;
#pragma unroll
            for (int j = 0; j < 4; ++j) {      // 4 k16 steps per 128B row
                uint32_t a[2][4], bf[4][4];
#pragma unroll
                for (int fi = 0; fi < 2; ++fi) {
                    uint32_t addr = stA + aBase[fi] + ((aK0 + j * 32) ^ aXor[fi]);
                    LDSM_X4(a[fi][0], a[fi][1], a[fi][2], a[fi][3], addr);
                }
#pragma unroll
                for (int half = 0; half < 4; ++half) {
                    int row = bRow[half] + tap;
                    uint32_t addr = stB + row * 128 + ((bK0 + j * 32) ^ ((row & 7) * 16));
                    LDSM_X4(bf[half][0], bf[half][1], bf[half][2], bf[half][3], addr);
                }
#pragma unroll
                for (int fi = 0; fi < 2; ++fi)
#pragma unroll
                    for (int ni = 0; ni < 8; ++ni)
                        mma16816(acc[fi][ni], a[fi][0], a[fi][1], a[fi][2], a[fi][3],
                                 bf[ni >> 1][(ni & 1) * 2], bf[ni >> 1][(ni & 1) * 2 + 1]);
            }
        }
        __syncthreads();
        if (c + 2 < NCHUNK) load_stage(c + 2, c & 1);
        CP_COMMIT();
    }

    // ---- epilogue: fmap bulk-copy to smem + bias/relu fp32 staging + coalesced sweep ----
    __syncthreads();                           // all compute done; safe to reuse stage smem
    float* stile = (float*)smem;               // [64][TS]
    unsigned char* sfmap = (unsigned char*)(smem + TILE_BYTES);   // [SPAN]

    // bulk coalesced fmap copy (overlaps with staging below)
    {
        const unsigned char* gf = g_fmap + ((size_t)b * NPB + (p0 >> 8)) * SPAN;
        for (int i = tid; i < SPAN / 16; i += 256)
            cp_async16(sb + TILE_BYTES + i * 16, gf + i * 16);
        CP_COMMIT();
    }

    // stage tile with bias + relu applied (fp32)
    {
        int hl = wm * 32 + (lane >> 2);
        int pl = wn * 64 + (lane & 3) * 2;
#pragma unroll
        for (int fi = 0; fi < 2; ++fi)
#pragma unroll
            for (int rr = 0; rr < 2; ++rr) {
                int hh = hl + fi * 16 + rr * 8;
                float cc = g_c2[h0 + hh];
#pragma unroll
                for (int ni = 0; ni < 8; ++ni) {
                    float2 v;
                    v.x = fmaxf(acc[fi][ni][rr * 2 + 0] + cc, 0.f);
                    v.y = fmaxf(acc[fi][ni][rr * 2 + 1] + cc, 0.f);
                    *(float2*)&stile[hh * TS + pl + ni * 8] = v;
                }
            }
    }

    bool lastblk = (p0 + TN >= PDIM);
    int fs = g_sd[b * PDIM + p0].x;
    int fe = lastblk ? g_total[b] : g_sd[b * PDIM + p0 + TN].x;
    int L = fe - fs;
    int Lw = lastblk ? (F - fs) : L;           // last block also zeroes the masked tail
    CP_WAIT0();
    __syncthreads();

    for (int h = wid; h < TM; h += 8) {
        float* orow = out + ((size_t)b * HDIM + h0 + h) * F + fs;
        const float* srow = stile + h * TS;
        for (int f = lane; f < Lw; f += 32)
            orow[f] = (f < L) ? srow[sfmap[f]] : 0.f;
    }
}

// ---------------- launch ----------------
extern "C" void kernel_launch(void* const* d_in, const int* in_sizes, int n_in,
                              void* d_out, int out_size) {
    const int* ids   = (const int*)d_in[0];
    const int* durs  = (const int*)d_in[1];
    const float* emb = (const float*)d_in[2];
    const float* w1  = (const float*)d_in[3];
    const float* b1  = (const float*)d_in[4];
    const float* g1  = (const float*)d_in[5];
    const float* be1 = (const float*)d_in[6];
    const float* m1  = (const float*)d_in[7];
    const float* v1  = (const float*)d_in[8];
    const float* w2  = (const float*)d_in[9];
    const float* b2  = (const float*)d_in[10];
    const float* g2  = (const float*)d_in[11];
    const float* be2 = (const float*)d_in[12];
    const float* m2  = (const float*)d_in[13];
    const float* v2  = (const float*)d_in[14];
    float* out = (float*)d_out;
    int F = out_size / (BDIM * HDIM);

    cudaFuncSetAttribute(k_gemm, cudaFuncAttributeMaxDynamicSharedMemorySize, GEMM_SMEM);

    k_tab<<<849, 512>>>(emb, w1, b1, g1, be1, m1, v1,
                        w2, b2, g2, be2, m2, v2, durs);                         // launch 0
    k_y1<<<dim3(BDIM, PDIM / 16), 256>>>(ids);                                  // launch 1
    k_gemm<<<dim3(PDIM / TN, HDIM / TM, BDIM), 256, GEMM_SMEM>>>(out, F);       // launch 2 (profiled)
}